// round 1
// baseline (speedup 1.0000x reference)
#include <cuda_runtime.h>
#include <cuda_bf16.h>

// ---------------------------------------------------------------------------
// Problem constants
// ---------------------------------------------------------------------------
#define BB 2
#define LL 2048
#define DD 1024
#define HH 16
#define HD 64
#define BL (BB*LL)           // 4096
#define EPS 1e-6f

// ---------------------------------------------------------------------------
// Scratch (device globals: the alloc-free scratch mechanism)
// ---------------------------------------------------------------------------
__device__ float g_xn [BL*DD];          // 16 MB  rmsnormed x
__device__ float g_cp [BL*3*DD];        // 48 MB  cond projection (scale/shift/gate interleaved x3)
__device__ float g_xm [BL*DD];          // 16 MB  modulated x
__device__ float g_qkv[BL*3*DD];        // 48 MB  qkv projection
__device__ float g_q  [BL*DD];          // 16 MB  [B,H,L,HD], pre-scaled by 1/8
__device__ float g_k  [BL*DD];          // 16 MB  [B,H,L,HD]
__device__ float g_v  [BL*DD];          // 16 MB  [B,H,L,HD]
__device__ float g_o  [BL*DD];          // 16 MB  attn out [B,H,L,HD]
__device__ float g_att[BL*DD];          // 16 MB  attn out [B,L,D]
__device__ float g_s  [(long)BB*HH*LL*LL]; // 536 MB scores / probs

// ---------------------------------------------------------------------------
// Generic batched register-blocked SGEMM.
//   C[z] = A[z] @ B[z]         (TRB=false : B is [K,N] row-major)
//   C[z] = A[z] @ B[z]^T       (TRB=true  : B is [N,K] row-major)
// All dims assumed divisible by tile sizes (true for every call here).
// EPI=true adds residual + gate (out-projection epilogue, hardcoded strides).
// ---------------------------------------------------------------------------
template<int BM,int BN,int BK,int TM,int TN,bool TRB,bool EPI>
__global__ void __launch_bounds__((BM/TM)*(BN/TN))
sgemm_kernel(const float* __restrict__ A, const float* __restrict__ Bg,
             float* __restrict__ C,
             int M, int N, int K,
             int lda, int ldb, int ldc,
             long sA, long sB, long sC,
             const float* __restrict__ Rres, const float* __restrict__ Ggate)
{
    constexpr int THREADS = (BM/TM)*(BN/TN);
    __shared__ float As[BK][BM];
    __shared__ float Bs[BK][BN];

    const int z = blockIdx.z;
    A  += (long)z * sA;
    Bg += (long)z * sB;
    C  += (long)z * sC;

    const int bm  = blockIdx.y * BM;
    const int bn  = blockIdx.x * BN;
    const int tid = threadIdx.x;
    const int tcol = tid % (BN/TN);
    const int trow = tid / (BN/TN);

    float acc[TM][TN];
#pragma unroll
    for (int i = 0; i < TM; i++)
#pragma unroll
        for (int j = 0; j < TN; j++) acc[i][j] = 0.f;

    // A-tile loader indices (also used for transposed-B loader)
    constexpr int K4  = BK/4;
    const int aRow = tid / K4;
    const int aCol = (tid % K4) * 4;
    constexpr int AST = THREADS / K4;
    // B-tile (NN) loader indices
    constexpr int N4  = BN/4;
    const int bRow = tid / N4;
    const int bCol = (tid % N4) * 4;
    constexpr int BST = THREADS / N4;

    for (int k0 = 0; k0 < K; k0 += BK) {
#pragma unroll
        for (int i = 0; i < BM; i += AST) {
            float4 v = *reinterpret_cast<const float4*>(
                &A[(long)(bm + aRow + i) * lda + k0 + aCol]);
            As[aCol+0][aRow+i] = v.x;
            As[aCol+1][aRow+i] = v.y;
            As[aCol+2][aRow+i] = v.z;
            As[aCol+3][aRow+i] = v.w;
        }
        if (!TRB) {
#pragma unroll
            for (int i = 0; i < BK; i += BST) {
                *reinterpret_cast<float4*>(&Bs[bRow+i][bCol]) =
                    *reinterpret_cast<const float4*>(
                        &Bg[(long)(k0 + bRow + i) * ldb + bn + bCol]);
            }
        } else {
#pragma unroll
            for (int i = 0; i < BN; i += AST) {
                float4 v = *reinterpret_cast<const float4*>(
                    &Bg[(long)(bn + aRow + i) * ldb + k0 + aCol]);
                Bs[aCol+0][aRow+i] = v.x;
                Bs[aCol+1][aRow+i] = v.y;
                Bs[aCol+2][aRow+i] = v.z;
                Bs[aCol+3][aRow+i] = v.w;
            }
        }
        __syncthreads();

#pragma unroll
        for (int k = 0; k < BK; k++) {
            float ar[TM], br[TN];
#pragma unroll
            for (int i = 0; i < TM; i += 4) {
                float4 v = *reinterpret_cast<const float4*>(&As[k][trow*TM + i]);
                ar[i] = v.x; ar[i+1] = v.y; ar[i+2] = v.z; ar[i+3] = v.w;
            }
#pragma unroll
            for (int j = 0; j < TN; j += 4) {
                float4 v = *reinterpret_cast<const float4*>(&Bs[k][tcol*TN + j]);
                br[j] = v.x; br[j+1] = v.y; br[j+2] = v.z; br[j+3] = v.w;
            }
#pragma unroll
            for (int i = 0; i < TM; i++)
#pragma unroll
                for (int j = 0; j < TN; j++)
                    acc[i][j] = fmaf(ar[i], br[j], acc[i][j]);
        }
        __syncthreads();
    }

#pragma unroll
    for (int i = 0; i < TM; i++) {
        const int r = bm + trow*TM + i;
#pragma unroll
        for (int j = 0; j < TN; j += 4) {
            const int c = bn + tcol*TN + j;
            float4 v;
            v.x = acc[i][j];   v.y = acc[i][j+1];
            v.z = acc[i][j+2]; v.w = acc[i][j+3];
            if (EPI) {
                v.x += Rres[(long)r*DD + c+0] + Ggate[(long)r*3*DD + 3*(c+0) + 2];
                v.y += Rres[(long)r*DD + c+1] + Ggate[(long)r*3*DD + 3*(c+1) + 2];
                v.z += Rres[(long)r*DD + c+2] + Ggate[(long)r*3*DD + 3*(c+2) + 2];
                v.w += Rres[(long)r*DD + c+3] + Ggate[(long)r*3*DD + 3*(c+3) + 2];
            }
            *reinterpret_cast<float4*>(&C[(long)r*ldc + c]) = v;
        }
    }
}

// ---------------------------------------------------------------------------
// RMSNorm: one block per (b,l) row of 1024, 256 threads, float4 per thread
// ---------------------------------------------------------------------------
__global__ void rmsnorm_kernel(const float* __restrict__ x,
                               const float* __restrict__ scale,
                               float* __restrict__ out)
{
    const int row = blockIdx.x;
    const float4 a = *((const float4*)(x + (long)row*DD) + threadIdx.x);
    float ss = a.x*a.x + a.y*a.y + a.z*a.z + a.w*a.w;

    __shared__ float red[8];
    for (int o = 16; o > 0; o >>= 1) ss += __shfl_xor_sync(~0u, ss, o);
    if ((threadIdx.x & 31) == 0) red[threadIdx.x >> 5] = ss;
    __syncthreads();
    __shared__ float rinv;
    if (threadIdx.x == 0) {
        float t = 0.f;
#pragma unroll
        for (int i = 0; i < 8; i++) t += red[i];
        rinv = rsqrtf(t * (1.0f/DD) + EPS);
    }
    __syncthreads();

    const float4 sc = *((const float4*)scale + threadIdx.x);
    float4 o4;
    o4.x = a.x * rinv * sc.x; o4.y = a.y * rinv * sc.y;
    o4.z = a.z * rinv * sc.z; o4.w = a.w * rinv * sc.w;
    *((float4*)(out + (long)row*DD) + threadIdx.x) = o4;
}

// ---------------------------------------------------------------------------
// AdaLN modulation: xm = xn * (1 + scale) + shift  (scale=cp[3d], shift=cp[3d+1])
// ---------------------------------------------------------------------------
__global__ void modulate_kernel(const float* __restrict__ xn,
                                const float* __restrict__ cp,
                                float* __restrict__ xm)
{
    const int idx = blockIdx.x * blockDim.x + threadIdx.x;  // 0..BL*DD
    const int row = idx >> 10;
    const int d   = idx & 1023;
    const long base = (long)row * (3*DD) + 3*d;
    xm[idx] = xn[idx] * (1.f + cp[base]) + cp[base + 1];
}

// ---------------------------------------------------------------------------
// RoPE + head scatter.  qkv row (3072 floats) staged in smem; outputs in
// [B,H,L,HD] layout.  q pre-scaled by 1/sqrt(HD)=0.125.
// qkv col for head h, dim d, sel: (d*H + h)*3 + sel; rotate pair: d^32 sign'd.
// sin = pos[2d], cos = pos[2d+1].
// ---------------------------------------------------------------------------
__global__ void rope_kernel(const float* __restrict__ qkv,
                            const float* __restrict__ pos,
                            float* __restrict__ q,
                            float* __restrict__ k,
                            float* __restrict__ v)
{
    const int bl = blockIdx.x;            // b*L + l
    const int b  = bl >> 11;
    const int l  = bl & (LL-1);
    __shared__ float srow[3*DD];
    __shared__ float spos[2*HD];

    const float4* src = (const float4*)(qkv + (long)bl * (3*DD));
    for (int i = threadIdx.x; i < (3*DD)/4; i += blockDim.x)
        ((float4*)srow)[i] = src[i];
    if (threadIdx.x < (2*HD)/4)
        ((float4*)spos)[threadIdx.x] =
            ((const float4*)(pos + (long)bl * (2*HD)))[threadIdx.x];
    __syncthreads();

    for (int idx = threadIdx.x; idx < DD; idx += blockDim.x) {
        const int h = idx >> 6;
        const int d = idx & (HD-1);
        const int c  = (d*HH + h) * 3;
        const int dp = (d < HD/2) ? d + HD/2 : d - HD/2;
        const int c2 = (dp*HH + h) * 3;
        const float sgn = (d < HD/2) ? -1.f : 1.f;
        const float s  = spos[2*d];
        const float ct = spos[2*d + 1];

        const float qo = srow[c]   * ct + sgn * srow[c2]   * s;
        const float ko = srow[c+1] * ct + sgn * srow[c2+1] * s;

        const long o = ((long)(b*HH + h) * LL + l) * HD + d;
        q[o] = qo * 0.125f;
        k[o] = ko;
        v[o] = srow[c + 2];
    }
}

// ---------------------------------------------------------------------------
// Softmax over rows of 2048 (in place).  8 elements per thread in registers.
// ---------------------------------------------------------------------------
__global__ void softmax_kernel(float* __restrict__ s)
{
    float* p = s + (long)blockIdx.x * LL;
    float4 v0 = ((float4*)p)[threadIdx.x];
    float4 v1 = ((float4*)p)[threadIdx.x + 256];

    float m = fmaxf(fmaxf(fmaxf(v0.x, v0.y), fmaxf(v0.z, v0.w)),
                    fmaxf(fmaxf(v1.x, v1.y), fmaxf(v1.z, v1.w)));
    __shared__ float red[8];
    for (int o = 16; o > 0; o >>= 1) m = fmaxf(m, __shfl_xor_sync(~0u, m, o));
    if ((threadIdx.x & 31) == 0) red[threadIdx.x >> 5] = m;
    __syncthreads();
    __shared__ float bm_s;
    if (threadIdx.x == 0) {
        float t = red[0];
#pragma unroll
        for (int i = 1; i < 8; i++) t = fmaxf(t, red[i]);
        bm_s = t;
    }
    __syncthreads();
    const float bm = bm_s;

    v0.x = __expf(v0.x - bm); v0.y = __expf(v0.y - bm);
    v0.z = __expf(v0.z - bm); v0.w = __expf(v0.w - bm);
    v1.x = __expf(v1.x - bm); v1.y = __expf(v1.y - bm);
    v1.z = __expf(v1.z - bm); v1.w = __expf(v1.w - bm);

    float ss = v0.x + v0.y + v0.z + v0.w + v1.x + v1.y + v1.z + v1.w;
    for (int o = 16; o > 0; o >>= 1) ss += __shfl_xor_sync(~0u, ss, o);
    if ((threadIdx.x & 31) == 0) red[threadIdx.x >> 5] = ss;
    __syncthreads();
    __shared__ float inv_s;
    if (threadIdx.x == 0) {
        float t = 0.f;
#pragma unroll
        for (int i = 0; i < 8; i++) t += red[i];
        inv_s = 1.f / t;
    }
    __syncthreads();
    const float inv = inv_s;

    v0.x *= inv; v0.y *= inv; v0.z *= inv; v0.w *= inv;
    v1.x *= inv; v1.y *= inv; v1.z *= inv; v1.w *= inv;
    ((float4*)p)[threadIdx.x]       = v0;
    ((float4*)p)[threadIdx.x + 256] = v1;
}

// ---------------------------------------------------------------------------
// [B,H,L,HD] -> [B,L,D] (d = h*HD + hd)
// ---------------------------------------------------------------------------
__global__ void permute_kernel(const float* __restrict__ o,
                               float* __restrict__ att)
{
    const int bl = blockIdx.x;
    const int b  = bl >> 11;
    const int l  = bl & (LL-1);
    for (int idx = threadIdx.x; idx < DD; idx += blockDim.x) {
        const int h = idx >> 6;
        const int d = idx & (HD-1);
        att[(long)bl*DD + idx] = o[((long)(b*HH + h)*LL + l)*HD + d];
    }
}

// ---------------------------------------------------------------------------
// Launch
// ---------------------------------------------------------------------------
extern "C" void kernel_launch(void* const* d_in, const int* in_sizes, int n_in,
                              void* d_out, int out_size)
{
    const float* x         = (const float*)d_in[0];
    const float* cond      = (const float*)d_in[1];
    const float* pos       = (const float*)d_in[2];
    const float* rms_scale = (const float*)d_in[3];
    const float* W_cond    = (const float*)d_in[4];
    const float* W_qkv     = (const float*)d_in[5];
    const float* W_out     = (const float*)d_in[6];
    float* out = (float*)d_out;

    float *xn, *cp, *xm, *qkv, *q, *k, *v, *o, *att, *s;
    cudaGetSymbolAddress((void**)&xn,  g_xn);
    cudaGetSymbolAddress((void**)&cp,  g_cp);
    cudaGetSymbolAddress((void**)&xm,  g_xm);
    cudaGetSymbolAddress((void**)&qkv, g_qkv);
    cudaGetSymbolAddress((void**)&q,   g_q);
    cudaGetSymbolAddress((void**)&k,   g_k);
    cudaGetSymbolAddress((void**)&v,   g_v);
    cudaGetSymbolAddress((void**)&o,   g_o);
    cudaGetSymbolAddress((void**)&att, g_att);
    cudaGetSymbolAddress((void**)&s,   g_s);

    // 1. RMSNorm
    rmsnorm_kernel<<<BL, 256>>>(x, rms_scale, xn);

    // 2. cond projection: cp = cond @ W_cond   (4096 x 3072 x 1024)
    sgemm_kernel<128,128,8,8,8,false,false><<<dim3(24,32,1), 256>>>(
        cond, W_cond, cp, BL, 3*DD, DD, DD, 3*DD, 3*DD, 0,0,0, nullptr, nullptr);

    // 3. modulate
    modulate_kernel<<<(BL*DD)/256, 256>>>(xn, cp, xm);

    // 4. qkv projection: qkv = xm @ W_qkv      (4096 x 3072 x 1024)
    sgemm_kernel<128,128,8,8,8,false,false><<<dim3(24,32,1), 256>>>(
        xm, W_qkv, qkv, BL, 3*DD, DD, DD, 3*DD, 3*DD, 0,0,0, nullptr, nullptr);

    // 5. RoPE + head scatter (q pre-scaled by 1/8)
    rope_kernel<<<BL, 256>>>(qkv, pos, q, k, v);

    // 6. scores: per (b,h)  S = q @ k^T   (2048 x 2048 x 64, 32 batches)
    sgemm_kernel<128,128,8,8,8,true,false><<<dim3(16,16,BB*HH), 256>>>(
        q, k, s, LL, LL, HD, HD, HD, LL,
        (long)LL*HD, (long)LL*HD, (long)LL*LL, nullptr, nullptr);

    // 7. softmax over last dim
    softmax_kernel<<<BB*HH*LL, 256>>>(s);

    // 8. out: per (b,h)  O = P @ v   (2048 x 64 x 2048, 32 batches)
    sgemm_kernel<128,64,16,8,4,false,false><<<dim3(1,16,BB*HH), 256>>>(
        s, v, o, LL, HD, LL, LL, HD, HD,
        (long)LL*LL, (long)LL*HD, (long)LL*HD, nullptr, nullptr);

    // 9. head merge to [B,L,D]
    permute_kernel<<<BL, 256>>>(o, att);

    // 10. out projection + residual + gate (fused epilogue)
    sgemm_kernel<128,128,8,8,8,false,true><<<dim3(8,32,1), 256>>>(
        att, W_out, out, BL, DD, DD, DD, DD, DD, 0,0,0, x, cp);
}

// round 4
// speedup vs baseline: 2.4068x; 2.4068x over previous
#include <cuda_runtime.h>
#include <cuda_bf16.h>
#include <cstdint>

// ---------------------------------------------------------------------------
// Problem constants
// ---------------------------------------------------------------------------
#define BB 2
#define LL 2048
#define DD 1024
#define HH 16
#define HD 64
#define BL (BB*LL)           // 4096
#define EPS 1e-6f

// ---------------------------------------------------------------------------
// Scratch (device globals: the sanctioned alloc-free scratch mechanism)
// ---------------------------------------------------------------------------
__device__ float g_xn [BL*DD];             // rmsnormed x
__device__ float g_cp [BL*3*DD];           // cond projection (scale/shift/gate x3 interleaved)
__device__ float g_xm [BL*DD];             // modulated x
__device__ float g_qkv[BL*3*DD];           // qkv projection
__device__ float g_q  [BL*DD];             // [B,H,L,HD], pre-scaled by 1/8
__device__ float g_kT [BL*DD];             // [B,H,HD,L]  (transposed K)
__device__ float g_v  [BL*DD];             // [B,H,L,HD]
__device__ float g_att[BL*DD];             // attn out [B,L,D]
__device__ float g_s  [(long)BB*HH*LL*LL]; // scores / probs

// ---------------------------------------------------------------------------
// tf32 helper: cvt.rna.tf32.f32 requires a .b32 destination register.
// Result bits are a valid fp32 pattern (low mantissa bits zeroed), so we can
// stage it through float smem exactly.
// ---------------------------------------------------------------------------
__device__ __forceinline__ float to_tf32(float x) {
    uint32_t r;
    asm("cvt.rna.tf32.f32 %0, %1;" : "=r"(r) : "f"(x));
    return __uint_as_float(r);
}

// ---------------------------------------------------------------------------
// Generic batched tf32 tensor-core GEMM (NN):  C[z] = A[z] @ B[z]
//   BM x BN x (BK=16) CTA tile, 8 warps in a 2x4 grid, warp tile (BM/2)x(BN/4)
//   mma.sync.m16n8k8.tf32.  fp32 accumulate.  All dims divide tile sizes.
//   C base per z:  C + (z/zmod)*sC_hi + (z%zmod)*sC_lo   (zmod=1 -> z*sC_hi)
//   EPI: out-projection epilogue  C += residual + gate  (hardcoded strides).
// ---------------------------------------------------------------------------
template<int BM, int BN, bool EPI>
__global__ void __launch_bounds__(256)
mma_gemm(const float* __restrict__ A, const float* __restrict__ Bg,
         float* __restrict__ C,
         int K, int lda, int ldb, int ldc,
         long sA, long sB, int zmod, long sC_hi, long sC_lo,
         const float* __restrict__ Rres, const float* __restrict__ Gg)
{
    constexpr int BK = 16;
    constexpr int WM = BM / 2;          // warp tile M (2 warp-rows)
    constexpr int WN = BN / 4;          // warp tile N (4 warp-cols)
    constexpr int MA = WM / 16;         // m16 atoms per warp
    constexpr int NA = WN / 8;          // n8 atoms per warp
    constexpr int ASTR = BK + 4;        // 20: conflict-free A frag loads
    constexpr int BSTR = BN + 8;        // stride%32==8: conflict-free B frag loads

    __shared__ float As[BM * ASTR];
    __shared__ float Bs[BK * BSTR];

    const int z = blockIdx.z;
    A += (long)z * sA;
    Bg += (long)z * sB;
    C += (long)(z / zmod) * sC_hi + (long)(z % zmod) * sC_lo;

    const int bm = blockIdx.y * BM;
    const int bn = blockIdx.x * BN;
    const int tid = threadIdx.x;
    const int lane = tid & 31;
    const int warp = tid >> 5;
    const int wm = warp >> 2;           // 0..1
    const int wn = warp & 3;            // 0..3
    const int g  = lane >> 2;           // group id 0..7
    const int tg = lane & 3;            // thread-in-group 0..3

    // global loader indices
    constexpr int A_IT = BM * BK / 1024;          // float4s per thread for A
    constexpr int A_RSTEP = 1024 / BK;            // 64
    const int arow = tid / (BK / 4);
    const int acol = (tid % (BK / 4)) * 4;
    constexpr int B_IT = BK * BN / 1024;          // float4s per thread for B
    constexpr int B_RSTEP = 1024 / BN;            // 8 (BN=128) / 16 (BN=64)
    const int brow = tid / (BN / 4);
    const int bcol = (tid % (BN / 4)) * 4;

    float acc[MA][NA][4];
#pragma unroll
    for (int i = 0; i < MA; i++)
#pragma unroll
        for (int j = 0; j < NA; j++)
#pragma unroll
            for (int c = 0; c < 4; c++) acc[i][j][c] = 0.f;

    float4 pa[A_IT], pb[B_IT];

    // prologue: load tile 0
#pragma unroll
    for (int i = 0; i < A_IT; i++)
        pa[i] = *reinterpret_cast<const float4*>(
            &A[(long)(bm + arow + i * A_RSTEP) * lda + acol]);
#pragma unroll
    for (int i = 0; i < B_IT; i++)
        pb[i] = *reinterpret_cast<const float4*>(
            &Bg[(long)(brow + i * B_RSTEP) * ldb + bn + bcol]);

    for (int k0 = 0; k0 < K; k0 += BK) {
        __syncthreads();   // previous compute done before overwriting smem
        // store (with tf32 rounding)
#pragma unroll
        for (int i = 0; i < A_IT; i++) {
            float4 v = pa[i];
            float* d = &As[(arow + i * A_RSTEP) * ASTR + acol];
            d[0] = to_tf32(v.x); d[1] = to_tf32(v.y);
            d[2] = to_tf32(v.z); d[3] = to_tf32(v.w);
        }
#pragma unroll
        for (int i = 0; i < B_IT; i++) {
            float4 v = pb[i];
            float* d = &Bs[(brow + i * B_RSTEP) * BSTR + bcol];
            d[0] = to_tf32(v.x); d[1] = to_tf32(v.y);
            d[2] = to_tf32(v.z); d[3] = to_tf32(v.w);
        }
        __syncthreads();

        // prefetch next tile
        if (k0 + BK < K) {
#pragma unroll
            for (int i = 0; i < A_IT; i++)
                pa[i] = *reinterpret_cast<const float4*>(
                    &A[(long)(bm + arow + i * A_RSTEP) * lda + k0 + BK + acol]);
#pragma unroll
            for (int i = 0; i < B_IT; i++)
                pb[i] = *reinterpret_cast<const float4*>(
                    &Bg[(long)(k0 + BK + brow + i * B_RSTEP) * ldb + bn + bcol]);
        }

        // compute: 2 k8 steps
#pragma unroll
        for (int ks = 0; ks < 2; ks++) {
            uint32_t af[MA][4], bf[NA][2];
#pragma unroll
            for (int i = 0; i < MA; i++) {
                const int r0 = (wm * WM + i * 16 + g) * ASTR + ks * 8 + tg;
                const int r1 = r0 + 8 * ASTR;
                af[i][0] = __float_as_uint(As[r0]);
                af[i][1] = __float_as_uint(As[r1]);
                af[i][2] = __float_as_uint(As[r0 + 4]);
                af[i][3] = __float_as_uint(As[r1 + 4]);
            }
#pragma unroll
            for (int j = 0; j < NA; j++) {
                const int c0 = (ks * 8 + tg) * BSTR + wn * WN + j * 8 + g;
                bf[j][0] = __float_as_uint(Bs[c0]);
                bf[j][1] = __float_as_uint(Bs[c0 + 4 * BSTR]);
            }
#pragma unroll
            for (int i = 0; i < MA; i++)
#pragma unroll
                for (int j = 0; j < NA; j++) {
                    asm volatile(
                        "mma.sync.aligned.m16n8k8.row.col.f32.tf32.tf32.f32 "
                        "{%0,%1,%2,%3}, {%4,%5,%6,%7}, {%8,%9}, {%0,%1,%2,%3};\n"
                        : "+f"(acc[i][j][0]), "+f"(acc[i][j][1]),
                          "+f"(acc[i][j][2]), "+f"(acc[i][j][3])
                        : "r"(af[i][0]), "r"(af[i][1]), "r"(af[i][2]), "r"(af[i][3]),
                          "r"(bf[j][0]), "r"(bf[j][1]));
                }
        }
    }

    // epilogue
#pragma unroll
    for (int i = 0; i < MA; i++) {
        const int r0 = bm + wm * WM + i * 16 + g;
#pragma unroll
        for (int j = 0; j < NA; j++) {
            const int c = bn + wn * WN + j * 8 + tg * 2;
            float2 v0 = make_float2(acc[i][j][0], acc[i][j][1]);
            float2 v1 = make_float2(acc[i][j][2], acc[i][j][3]);
            if (EPI) {
                v0.x += Rres[(long)r0 * DD + c]     + Gg[(long)r0 * 3 * DD + 3 * c + 2];
                v0.y += Rres[(long)r0 * DD + c + 1] + Gg[(long)r0 * 3 * DD + 3 * (c + 1) + 2];
                v1.x += Rres[(long)(r0 + 8) * DD + c]     + Gg[(long)(r0 + 8) * 3 * DD + 3 * c + 2];
                v1.y += Rres[(long)(r0 + 8) * DD + c + 1] + Gg[(long)(r0 + 8) * 3 * DD + 3 * (c + 1) + 2];
            }
            *reinterpret_cast<float2*>(&C[(long)r0 * ldc + c]) = v0;
            *reinterpret_cast<float2*>(&C[(long)(r0 + 8) * ldc + c]) = v1;
        }
    }
}

// ---------------------------------------------------------------------------
// RMSNorm: one block per (b,l) row of 1024, 256 threads, float4 per thread
// ---------------------------------------------------------------------------
__global__ void rmsnorm_kernel(const float* __restrict__ x,
                               const float* __restrict__ scale,
                               float* __restrict__ out)
{
    const int row = blockIdx.x;
    const float4 a = *((const float4*)(x + (long)row * DD) + threadIdx.x);
    float ss = a.x * a.x + a.y * a.y + a.z * a.z + a.w * a.w;

    __shared__ float red[8];
    for (int o = 16; o > 0; o >>= 1) ss += __shfl_xor_sync(~0u, ss, o);
    if ((threadIdx.x & 31) == 0) red[threadIdx.x >> 5] = ss;
    __syncthreads();
    __shared__ float rinv;
    if (threadIdx.x == 0) {
        float t = 0.f;
#pragma unroll
        for (int i = 0; i < 8; i++) t += red[i];
        rinv = rsqrtf(t * (1.0f / DD) + EPS);
    }
    __syncthreads();

    const float4 sc = *((const float4*)scale + threadIdx.x);
    float4 o4;
    o4.x = a.x * rinv * sc.x; o4.y = a.y * rinv * sc.y;
    o4.z = a.z * rinv * sc.z; o4.w = a.w * rinv * sc.w;
    *((float4*)(out + (long)row * DD) + threadIdx.x) = o4;
}

// ---------------------------------------------------------------------------
// AdaLN modulation: xm = xn * (1 + scale) + shift
// ---------------------------------------------------------------------------
__global__ void modulate_kernel(const float* __restrict__ xn,
                                const float* __restrict__ cp,
                                float* __restrict__ xm)
{
    const int idx = blockIdx.x * blockDim.x + threadIdx.x;
    const int row = idx >> 10;
    const int d = idx & 1023;
    const long base = (long)row * (3 * DD) + 3 * d;
    xm[idx] = xn[idx] * (1.f + cp[base]) + cp[base + 1];
}

// ---------------------------------------------------------------------------
// RoPE + head scatter.  q -> [B,H,L,HD] (x 1/8), kT -> [B,H,HD,L], v -> [B,H,L,HD]
// ---------------------------------------------------------------------------
__global__ void rope_kernel(const float* __restrict__ qkv,
                            const float* __restrict__ pos,
                            float* __restrict__ q,
                            float* __restrict__ kT,
                            float* __restrict__ v)
{
    const int bl = blockIdx.x;
    const int b = bl >> 11;
    const int l = bl & (LL - 1);
    __shared__ float srow[3 * DD];
    __shared__ float spos[2 * HD];

    const float4* src = (const float4*)(qkv + (long)bl * (3 * DD));
    for (int i = threadIdx.x; i < (3 * DD) / 4; i += blockDim.x)
        ((float4*)srow)[i] = src[i];
    if (threadIdx.x < (2 * HD) / 4)
        ((float4*)spos)[threadIdx.x] =
            ((const float4*)(pos + (long)bl * (2 * HD)))[threadIdx.x];
    __syncthreads();

    for (int idx = threadIdx.x; idx < DD; idx += blockDim.x) {
        const int h = idx >> 6;
        const int d = idx & (HD - 1);
        const int c = (d * HH + h) * 3;
        const int dp = (d < HD / 2) ? d + HD / 2 : d - HD / 2;
        const int c2 = (dp * HH + h) * 3;
        const float sgn = (d < HD / 2) ? -1.f : 1.f;
        const float s = spos[2 * d];
        const float ct = spos[2 * d + 1];

        const float qo = srow[c] * ct + sgn * srow[c2] * s;
        const float ko = srow[c + 1] * ct + sgn * srow[c2 + 1] * s;

        const long o = ((long)(b * HH + h) * LL + l) * HD + d;
        q[o] = qo * 0.125f;
        kT[((long)(b * HH + h) * HD + d) * LL + l] = ko;
        v[o] = srow[c + 2];
    }
}

// ---------------------------------------------------------------------------
// Softmax over rows of 2048 (in place), 8 elements per thread in registers.
// ---------------------------------------------------------------------------
__global__ void softmax_kernel(float* __restrict__ s)
{
    float* p = s + (long)blockIdx.x * LL;
    float4 v0 = ((float4*)p)[threadIdx.x];
    float4 v1 = ((float4*)p)[threadIdx.x + 256];

    float m = fmaxf(fmaxf(fmaxf(v0.x, v0.y), fmaxf(v0.z, v0.w)),
                    fmaxf(fmaxf(v1.x, v1.y), fmaxf(v1.z, v1.w)));
    __shared__ float red[8];
    for (int o = 16; o > 0; o >>= 1) m = fmaxf(m, __shfl_xor_sync(~0u, m, o));
    if ((threadIdx.x & 31) == 0) red[threadIdx.x >> 5] = m;
    __syncthreads();
    __shared__ float bm_s;
    if (threadIdx.x == 0) {
        float t = red[0];
#pragma unroll
        for (int i = 1; i < 8; i++) t = fmaxf(t, red[i]);
        bm_s = t;
    }
    __syncthreads();
    const float bm = bm_s;

    v0.x = __expf(v0.x - bm); v0.y = __expf(v0.y - bm);
    v0.z = __expf(v0.z - bm); v0.w = __expf(v0.w - bm);
    v1.x = __expf(v1.x - bm); v1.y = __expf(v1.y - bm);
    v1.z = __expf(v1.z - bm); v1.w = __expf(v1.w - bm);

    float ss = v0.x + v0.y + v0.z + v0.w + v1.x + v1.y + v1.z + v1.w;
    for (int o = 16; o > 0; o >>= 1) ss += __shfl_xor_sync(~0u, ss, o);
    if ((threadIdx.x & 31) == 0) red[threadIdx.x >> 5] = ss;
    __syncthreads();
    __shared__ float inv_s;
    if (threadIdx.x == 0) {
        float t = 0.f;
#pragma unroll
        for (int i = 0; i < 8; i++) t += red[i];
        inv_s = 1.f / t;
    }
    __syncthreads();
    const float inv = inv_s;

    v0.x *= inv; v0.y *= inv; v0.z *= inv; v0.w *= inv;
    v1.x *= inv; v1.y *= inv; v1.z *= inv; v1.w *= inv;
    ((float4*)p)[threadIdx.x] = v0;
    ((float4*)p)[threadIdx.x + 256] = v1;
}

// ---------------------------------------------------------------------------
// Launch
// ---------------------------------------------------------------------------
extern "C" void kernel_launch(void* const* d_in, const int* in_sizes, int n_in,
                              void* d_out, int out_size)
{
    const float* x         = (const float*)d_in[0];
    const float* cond      = (const float*)d_in[1];
    const float* pos       = (const float*)d_in[2];
    const float* rms_scale = (const float*)d_in[3];
    const float* W_cond    = (const float*)d_in[4];
    const float* W_qkv     = (const float*)d_in[5];
    const float* W_out     = (const float*)d_in[6];
    float* out = (float*)d_out;

    float *xn, *cp, *xm, *qkv, *q, *kT, *v, *att, *s;
    cudaGetSymbolAddress((void**)&xn,  g_xn);
    cudaGetSymbolAddress((void**)&cp,  g_cp);
    cudaGetSymbolAddress((void**)&xm,  g_xm);
    cudaGetSymbolAddress((void**)&qkv, g_qkv);
    cudaGetSymbolAddress((void**)&q,   g_q);
    cudaGetSymbolAddress((void**)&kT,  g_kT);
    cudaGetSymbolAddress((void**)&v,   g_v);
    cudaGetSymbolAddress((void**)&att, g_att);
    cudaGetSymbolAddress((void**)&s,   g_s);

    // 1. RMSNorm
    rmsnorm_kernel<<<BL, 256>>>(x, rms_scale, xn);

    // 2. cond projection: cp = cond @ W_cond   (4096 x 3072 x 1024)
    mma_gemm<128, 128, false><<<dim3(24, 32, 1), 256>>>(
        cond, W_cond, cp, DD, DD, 3 * DD, 3 * DD,
        0, 0, 1, 0, 0, nullptr, nullptr);

    // 3. modulate
    modulate_kernel<<<(BL * DD) / 256, 256>>>(xn, cp, xm);

    // 4. qkv projection
    mma_gemm<128, 128, false><<<dim3(24, 32, 1), 256>>>(
        xm, W_qkv, qkv, DD, DD, 3 * DD, 3 * DD,
        0, 0, 1, 0, 0, nullptr, nullptr);

    // 5. RoPE + head scatter (q pre-scaled by 1/8, k transposed)
    rope_kernel<<<BL, 256>>>(qkv, pos, q, kT, v);

    // 6. scores: per (b,h)  S = q @ kT   (2048 x 2048 x 64, 32 batches, NN)
    mma_gemm<128, 128, false><<<dim3(16, 16, BB * HH), 256>>>(
        q, kT, s, HD, HD, LL, LL,
        (long)LL * HD, (long)LL * HD, 1, (long)LL * LL, 0, nullptr, nullptr);

    // 7. softmax
    softmax_kernel<<<BB * HH * LL, 256>>>(s);

    // 8. out: per (b,h)  att[b, l, h*64 + :] = P @ v   (2048 x 64 x 2048)
    mma_gemm<128, 64, false><<<dim3(1, 16, BB * HH), 256>>>(
        s, v, att, LL, LL, HD, DD,
        (long)LL * LL, (long)LL * HD, HH, (long)LL * DD, HD, nullptr, nullptr);

    // 9. out projection + residual + gate (fused epilogue)
    mma_gemm<128, 128, true><<<dim3(8, 32, 1), 256>>>(
        att, W_out, out, DD, DD, DD, DD,
        0, 0, 1, 0, 0, x, cp);
}

// round 5
// speedup vs baseline: 2.8786x; 1.1960x over previous
#include <cuda_runtime.h>
#include <cuda_bf16.h>
#include <cstdint>

// ---------------------------------------------------------------------------
// Problem constants
// ---------------------------------------------------------------------------
#define BB 2
#define LL 2048
#define DD 1024
#define HH 16
#define HD 64
#define BL (BB*LL)           // 4096
#define EPS 1e-6f

// ---------------------------------------------------------------------------
// Scratch (device globals: the sanctioned alloc-free scratch mechanism)
// ---------------------------------------------------------------------------
__device__ float g_xn [BL*DD];             // rmsnormed x
__device__ float g_cp [BL*3*DD];           // cond projection (scale/shift/gate x3 interleaved)
__device__ float g_xm [BL*DD];             // modulated x
__device__ float g_qkv[BL*3*DD];           // qkv projection
__device__ float g_q  [BL*DD];             // [B,H,L,HD], pre-scaled by 1/8
__device__ float g_kT [BL*DD];             // [B,H,HD,L]  (transposed K)
__device__ float g_v  [BL*DD];             // [B,H,L,HD]
__device__ float g_att[BL*DD];             // attn out [B,L,D]

// ---------------------------------------------------------------------------
// tf32 helper: cvt.rna.tf32.f32 requires a .b32 destination register.
// ---------------------------------------------------------------------------
__device__ __forceinline__ float to_tf32(float x) {
    uint32_t r;
    asm("cvt.rna.tf32.f32 %0, %1;" : "=r"(r) : "f"(x));
    return __uint_as_float(r);
}

__device__ __forceinline__ void mma_tf32(float acc[4],
                                         uint32_t a0, uint32_t a1, uint32_t a2, uint32_t a3,
                                         uint32_t b0, uint32_t b1) {
    asm volatile(
        "mma.sync.aligned.m16n8k8.row.col.f32.tf32.tf32.f32 "
        "{%0,%1,%2,%3}, {%4,%5,%6,%7}, {%8,%9}, {%0,%1,%2,%3};\n"
        : "+f"(acc[0]), "+f"(acc[1]), "+f"(acc[2]), "+f"(acc[3])
        : "r"(a0), "r"(a1), "r"(a2), "r"(a3), "r"(b0), "r"(b1));
}

// ---------------------------------------------------------------------------
// Generic batched tf32 tensor-core GEMM (NN):  C[z] = A[z] @ B[z]
// (verified in R4; unchanged)
// ---------------------------------------------------------------------------
template<int BM, int BN, bool EPI>
__global__ void __launch_bounds__(256)
mma_gemm(const float* __restrict__ A, const float* __restrict__ Bg,
         float* __restrict__ C,
         int K, int lda, int ldb, int ldc,
         long sA, long sB, int zmod, long sC_hi, long sC_lo,
         const float* __restrict__ Rres, const float* __restrict__ Gg)
{
    constexpr int BK = 16;
    constexpr int WM = BM / 2;
    constexpr int WN = BN / 4;
    constexpr int MA = WM / 16;
    constexpr int NA = WN / 8;
    constexpr int ASTR = BK + 4;
    constexpr int BSTR = BN + 8;

    __shared__ float As[BM * ASTR];
    __shared__ float Bs[BK * BSTR];

    const int z = blockIdx.z;
    A += (long)z * sA;
    Bg += (long)z * sB;
    C += (long)(z / zmod) * sC_hi + (long)(z % zmod) * sC_lo;

    const int bm = blockIdx.y * BM;
    const int bn = blockIdx.x * BN;
    const int tid = threadIdx.x;
    const int lane = tid & 31;
    const int warp = tid >> 5;
    const int wm = warp >> 2;
    const int wn = warp & 3;
    const int g  = lane >> 2;
    const int tg = lane & 3;

    constexpr int A_IT = BM * BK / 1024;
    constexpr int A_RSTEP = 1024 / BK;
    const int arow = tid / (BK / 4);
    const int acol = (tid % (BK / 4)) * 4;
    constexpr int B_IT = BK * BN / 1024;
    constexpr int B_RSTEP = 1024 / BN;
    const int brow = tid / (BN / 4);
    const int bcol = (tid % (BN / 4)) * 4;

    float acc[MA][NA][4];
#pragma unroll
    for (int i = 0; i < MA; i++)
#pragma unroll
        for (int j = 0; j < NA; j++)
#pragma unroll
            for (int c = 0; c < 4; c++) acc[i][j][c] = 0.f;

    float4 pa[A_IT], pb[B_IT];

#pragma unroll
    for (int i = 0; i < A_IT; i++)
        pa[i] = *reinterpret_cast<const float4*>(
            &A[(long)(bm + arow + i * A_RSTEP) * lda + acol]);
#pragma unroll
    for (int i = 0; i < B_IT; i++)
        pb[i] = *reinterpret_cast<const float4*>(
            &Bg[(long)(brow + i * B_RSTEP) * ldb + bn + bcol]);

    for (int k0 = 0; k0 < K; k0 += BK) {
        __syncthreads();
#pragma unroll
        for (int i = 0; i < A_IT; i++) {
            float4 v = pa[i];
            float* d = &As[(arow + i * A_RSTEP) * ASTR + acol];
            d[0] = to_tf32(v.x); d[1] = to_tf32(v.y);
            d[2] = to_tf32(v.z); d[3] = to_tf32(v.w);
        }
#pragma unroll
        for (int i = 0; i < B_IT; i++) {
            float4 v = pb[i];
            float* d = &Bs[(brow + i * B_RSTEP) * BSTR + bcol];
            d[0] = to_tf32(v.x); d[1] = to_tf32(v.y);
            d[2] = to_tf32(v.z); d[3] = to_tf32(v.w);
        }
        __syncthreads();

        if (k0 + BK < K) {
#pragma unroll
            for (int i = 0; i < A_IT; i++)
                pa[i] = *reinterpret_cast<const float4*>(
                    &A[(long)(bm + arow + i * A_RSTEP) * lda + k0 + BK + acol]);
#pragma unroll
            for (int i = 0; i < B_IT; i++)
                pb[i] = *reinterpret_cast<const float4*>(
                    &Bg[(long)(k0 + BK + brow + i * B_RSTEP) * ldb + bn + bcol]);
        }

#pragma unroll
        for (int ks = 0; ks < 2; ks++) {
            uint32_t af[MA][4], bf[NA][2];
#pragma unroll
            for (int i = 0; i < MA; i++) {
                const int r0 = (wm * WM + i * 16 + g) * ASTR + ks * 8 + tg;
                const int r1 = r0 + 8 * ASTR;
                af[i][0] = __float_as_uint(As[r0]);
                af[i][1] = __float_as_uint(As[r1]);
                af[i][2] = __float_as_uint(As[r0 + 4]);
                af[i][3] = __float_as_uint(As[r1 + 4]);
            }
#pragma unroll
            for (int j = 0; j < NA; j++) {
                const int c0 = (ks * 8 + tg) * BSTR + wn * WN + j * 8 + g;
                bf[j][0] = __float_as_uint(Bs[c0]);
                bf[j][1] = __float_as_uint(Bs[c0 + 4 * BSTR]);
            }
#pragma unroll
            for (int i = 0; i < MA; i++)
#pragma unroll
                for (int j = 0; j < NA; j++)
                    mma_tf32(acc[i][j], af[i][0], af[i][1], af[i][2], af[i][3],
                             bf[j][0], bf[j][1]);
        }
    }

#pragma unroll
    for (int i = 0; i < MA; i++) {
        const int r0 = bm + wm * WM + i * 16 + g;
#pragma unroll
        for (int j = 0; j < NA; j++) {
            const int c = bn + wn * WN + j * 8 + tg * 2;
            float2 v0 = make_float2(acc[i][j][0], acc[i][j][1]);
            float2 v1 = make_float2(acc[i][j][2], acc[i][j][3]);
            if (EPI) {
                v0.x += Rres[(long)r0 * DD + c]     + Gg[(long)r0 * 3 * DD + 3 * c + 2];
                v0.y += Rres[(long)r0 * DD + c + 1] + Gg[(long)r0 * 3 * DD + 3 * (c + 1) + 2];
                v1.x += Rres[(long)(r0 + 8) * DD + c]     + Gg[(long)(r0 + 8) * 3 * DD + 3 * c + 2];
                v1.y += Rres[(long)(r0 + 8) * DD + c + 1] + Gg[(long)(r0 + 8) * 3 * DD + 3 * (c + 1) + 2];
            }
            *reinterpret_cast<float2*>(&C[(long)r0 * ldc + c]) = v0;
            *reinterpret_cast<float2*>(&C[(long)(r0 + 8) * ldc + c]) = v1;
        }
    }
}

// ---------------------------------------------------------------------------
// Flash attention: per CTA = one (b,h) and one 128-row Q tile.
//   Loop over 32 K/V chunks of 64: S = Q@Kt (tf32 mma), online softmax in
//   registers (8 m-warps x 1 n-warp -> row stats reduce within a quad),
//   P staged through per-warp-private smem stripe, O += P@V (tf32 mma).
//   Writes O directly into [B,L,D] layout (att). Q pre-scaled by 1/8.
// ---------------------------------------------------------------------------
#define FQ_STR 68   // 64 + 4
#define FB_STR 72   // 64 + 8
#define F_SQ   0
#define F_SK   (128*FQ_STR)                 // 8704
#define F_SV   (F_SK + 64*FB_STR)           // 13312
#define F_SP   (F_SV + 64*FB_STR)           // 17920
#define F_TOT  (F_SP + 128*FQ_STR)          // 26624 floats = 106496 B

__global__ void __launch_bounds__(256)
flash_kernel(const float* __restrict__ q, const float* __restrict__ kT,
             const float* __restrict__ v, float* __restrict__ att)
{
    extern __shared__ float sm[];
    float* sQ = sm + F_SQ;
    float* sK = sm + F_SK;
    float* sV = sm + F_SV;
    float* sP = sm + F_SP;

    const int bh = blockIdx.y;          // b*HH + h
    const int b  = bh >> 4;
    const int h  = bh & (HH - 1);
    const int m0 = blockIdx.x * 128;
    const int tid = threadIdx.x;
    const int lane = tid & 31;
    const int warp = tid >> 5;
    const int g  = lane >> 2;
    const int tg = lane & 3;

    // load Q tile [128][64] -> sQ (tf32)
    const float* qbase = q + ((long)bh * LL + m0) * HD;
    for (int i = tid; i < 128 * 16; i += 256) {
        const int r = i >> 4, c4 = (i & 15) * 4;
        float4 t = *reinterpret_cast<const float4*>(&qbase[(long)r * HD + c4]);
        float* d = &sQ[r * FQ_STR + c4];
        d[0] = to_tf32(t.x); d[1] = to_tf32(t.y);
        d[2] = to_tf32(t.z); d[3] = to_tf32(t.w);
    }

    float accO[8][4];
#pragma unroll
    for (int j = 0; j < 8; j++)
#pragma unroll
        for (int c = 0; c < 4; c++) accO[j][c] = 0.f;
    float mrow0 = -1e30f, mrow1 = -1e30f, lrow0 = 0.f, lrow1 = 0.f;

    const float* kbase = kT + (long)bh * HD * LL;
    const float* vbase = v + (long)bh * LL * HD;
    const int prow = (warp * 16 + g) * FQ_STR;   // this thread's sP rows

    for (int j0 = 0; j0 < LL; j0 += 64) {
        __syncthreads();   // all warps done reading sK/sV from previous iter
        // load K chunk: sK[hd][n] = kT[hd][j0+n]  (rows contiguous in l)
        for (int i = tid; i < 64 * 16; i += 256) {
            const int r = i >> 4, c4 = (i & 15) * 4;
            float4 t = *reinterpret_cast<const float4*>(&kbase[(long)r * LL + j0 + c4]);
            float* d = &sK[r * FB_STR + c4];
            d[0] = to_tf32(t.x); d[1] = to_tf32(t.y);
            d[2] = to_tf32(t.z); d[3] = to_tf32(t.w);
        }
        // load V chunk: sV[lv][hd]
        for (int i = tid; i < 64 * 16; i += 256) {
            const int r = i >> 4, c4 = (i & 15) * 4;
            float4 t = *reinterpret_cast<const float4*>(&vbase[(long)(j0 + r) * HD + c4]);
            float* d = &sV[r * FB_STR + c4];
            d[0] = to_tf32(t.x); d[1] = to_tf32(t.y);
            d[2] = to_tf32(t.z); d[3] = to_tf32(t.w);
        }
        __syncthreads();

        // S = Q_tile(warp rows) @ K_chunk : 16x64, k=64
        float s[8][4];
#pragma unroll
        for (int j = 0; j < 8; j++)
#pragma unroll
            for (int c = 0; c < 4; c++) s[j][c] = 0.f;
#pragma unroll
        for (int ks = 0; ks < 8; ks++) {
            const int r0 = prow + ks * 8 + tg;
            const uint32_t a0 = __float_as_uint(sQ[r0]);
            const uint32_t a1 = __float_as_uint(sQ[r0 + 8 * FQ_STR]);
            const uint32_t a2 = __float_as_uint(sQ[r0 + 4]);
            const uint32_t a3 = __float_as_uint(sQ[r0 + 8 * FQ_STR + 4]);
#pragma unroll
            for (int j = 0; j < 8; j++) {
                const int c0 = (ks * 8 + tg) * FB_STR + j * 8 + g;
                mma_tf32(s[j], a0, a1, a2, a3,
                         __float_as_uint(sK[c0]),
                         __float_as_uint(sK[c0 + 4 * FB_STR]));
            }
        }

        // online softmax: rows (warp*16+g) and (+8); stats reduce over quad
        float mx0 = -1e30f, mx1 = -1e30f;
#pragma unroll
        for (int j = 0; j < 8; j++) {
            mx0 = fmaxf(mx0, fmaxf(s[j][0], s[j][1]));
            mx1 = fmaxf(mx1, fmaxf(s[j][2], s[j][3]));
        }
        mx0 = fmaxf(mx0, __shfl_xor_sync(~0u, mx0, 1));
        mx0 = fmaxf(mx0, __shfl_xor_sync(~0u, mx0, 2));
        mx1 = fmaxf(mx1, __shfl_xor_sync(~0u, mx1, 1));
        mx1 = fmaxf(mx1, __shfl_xor_sync(~0u, mx1, 2));

        const float mn0 = fmaxf(mrow0, mx0);
        const float mn1 = fmaxf(mrow1, mx1);
        const float al0 = __expf(mrow0 - mn0);
        const float al1 = __expf(mrow1 - mn1);
        mrow0 = mn0; mrow1 = mn1;

        float ps0 = 0.f, ps1 = 0.f;
#pragma unroll
        for (int j = 0; j < 8; j++) {
            s[j][0] = __expf(s[j][0] - mn0);
            s[j][1] = __expf(s[j][1] - mn0);
            s[j][2] = __expf(s[j][2] - mn1);
            s[j][3] = __expf(s[j][3] - mn1);
            ps0 += s[j][0] + s[j][1];
            ps1 += s[j][2] + s[j][3];
        }
        ps0 += __shfl_xor_sync(~0u, ps0, 1);
        ps0 += __shfl_xor_sync(~0u, ps0, 2);
        ps1 += __shfl_xor_sync(~0u, ps1, 1);
        ps1 += __shfl_xor_sync(~0u, ps1, 2);
        lrow0 = lrow0 * al0 + ps0;
        lrow1 = lrow1 * al1 + ps1;

#pragma unroll
        for (int j = 0; j < 8; j++) {
            accO[j][0] *= al0; accO[j][1] *= al0;
            accO[j][2] *= al1; accO[j][3] *= al1;
        }

        // stage P in per-warp-private sP stripe (rows warp*16 .. +15)
#pragma unroll
        for (int j = 0; j < 8; j++) {
            const int c = j * 8 + tg * 2;
            sP[prow + c]     = to_tf32(s[j][0]);
            sP[prow + c + 1] = to_tf32(s[j][1]);
            sP[prow + 8 * FQ_STR + c]     = to_tf32(s[j][2]);
            sP[prow + 8 * FQ_STR + c + 1] = to_tf32(s[j][3]);
        }
        __syncwarp();

        // O += P(16x64) @ V(64x64)
#pragma unroll
        for (int ks = 0; ks < 8; ks++) {
            const int r0 = prow + ks * 8 + tg;
            const uint32_t a0 = __float_as_uint(sP[r0]);
            const uint32_t a1 = __float_as_uint(sP[r0 + 8 * FQ_STR]);
            const uint32_t a2 = __float_as_uint(sP[r0 + 4]);
            const uint32_t a3 = __float_as_uint(sP[r0 + 8 * FQ_STR + 4]);
#pragma unroll
            for (int j = 0; j < 8; j++) {
                const int c0 = (ks * 8 + tg) * FB_STR + j * 8 + g;
                mma_tf32(accO[j], a0, a1, a2, a3,
                         __float_as_uint(sV[c0]),
                         __float_as_uint(sV[c0 + 4 * FB_STR]));
            }
        }
    }

    // epilogue: O /= l, write to att[B,L,D]
    const float inv0 = 1.f / lrow0;
    const float inv1 = 1.f / lrow1;
    float* obase = att + ((long)(b * LL + m0 + warp * 16 + g)) * DD + h * HD;
#pragma unroll
    for (int j = 0; j < 8; j++) {
        const int c = j * 8 + tg * 2;
        *reinterpret_cast<float2*>(&obase[c]) =
            make_float2(accO[j][0] * inv0, accO[j][1] * inv0);
        *reinterpret_cast<float2*>(&obase[(long)8 * DD + c]) =
            make_float2(accO[j][2] * inv1, accO[j][3] * inv1);
    }
}

// ---------------------------------------------------------------------------
// RMSNorm
// ---------------------------------------------------------------------------
__global__ void rmsnorm_kernel(const float* __restrict__ x,
                               const float* __restrict__ scale,
                               float* __restrict__ out)
{
    const int row = blockIdx.x;
    const float4 a = *((const float4*)(x + (long)row * DD) + threadIdx.x);
    float ss = a.x * a.x + a.y * a.y + a.z * a.z + a.w * a.w;

    __shared__ float red[8];
    for (int o = 16; o > 0; o >>= 1) ss += __shfl_xor_sync(~0u, ss, o);
    if ((threadIdx.x & 31) == 0) red[threadIdx.x >> 5] = ss;
    __syncthreads();
    __shared__ float rinv;
    if (threadIdx.x == 0) {
        float t = 0.f;
#pragma unroll
        for (int i = 0; i < 8; i++) t += red[i];
        rinv = rsqrtf(t * (1.0f / DD) + EPS);
    }
    __syncthreads();

    const float4 sc = *((const float4*)scale + threadIdx.x);
    float4 o4;
    o4.x = a.x * rinv * sc.x; o4.y = a.y * rinv * sc.y;
    o4.z = a.z * rinv * sc.z; o4.w = a.w * rinv * sc.w;
    *((float4*)(out + (long)row * DD) + threadIdx.x) = o4;
}

// ---------------------------------------------------------------------------
// AdaLN modulation
// ---------------------------------------------------------------------------
__global__ void modulate_kernel(const float* __restrict__ xn,
                                const float* __restrict__ cp,
                                float* __restrict__ xm)
{
    const int idx = blockIdx.x * blockDim.x + threadIdx.x;
    const int row = idx >> 10;
    const int d = idx & 1023;
    const long base = (long)row * (3 * DD) + 3 * d;
    xm[idx] = xn[idx] * (1.f + cp[base]) + cp[base + 1];
}

// ---------------------------------------------------------------------------
// RoPE + head scatter.  q -> [B,H,L,HD] (x 1/8), kT -> [B,H,HD,L], v -> [B,H,L,HD]
// ---------------------------------------------------------------------------
__global__ void rope_kernel(const float* __restrict__ qkv,
                            const float* __restrict__ pos,
                            float* __restrict__ q,
                            float* __restrict__ kT,
                            float* __restrict__ v)
{
    const int bl = blockIdx.x;
    const int b = bl >> 11;
    const int l = bl & (LL - 1);
    __shared__ float srow[3 * DD];
    __shared__ float spos[2 * HD];

    const float4* src = (const float4*)(qkv + (long)bl * (3 * DD));
    for (int i = threadIdx.x; i < (3 * DD) / 4; i += blockDim.x)
        ((float4*)srow)[i] = src[i];
    if (threadIdx.x < (2 * HD) / 4)
        ((float4*)spos)[threadIdx.x] =
            ((const float4*)(pos + (long)bl * (2 * HD)))[threadIdx.x];
    __syncthreads();

    for (int idx = threadIdx.x; idx < DD; idx += blockDim.x) {
        const int h = idx >> 6;
        const int d = idx & (HD - 1);
        const int c = (d * HH + h) * 3;
        const int dp = (d < HD / 2) ? d + HD / 2 : d - HD / 2;
        const int c2 = (dp * HH + h) * 3;
        const float sgn = (d < HD / 2) ? -1.f : 1.f;
        const float s = spos[2 * d];
        const float ct = spos[2 * d + 1];

        const float qo = srow[c] * ct + sgn * srow[c2] * s;
        const float ko = srow[c + 1] * ct + sgn * srow[c2 + 1] * s;

        const long o = ((long)(b * HH + h) * LL + l) * HD + d;
        q[o] = qo * 0.125f;
        kT[((long)(b * HH + h) * HD + d) * LL + l] = ko;
        v[o] = srow[c + 2];
    }
}

// ---------------------------------------------------------------------------
// Launch
// ---------------------------------------------------------------------------
extern "C" void kernel_launch(void* const* d_in, const int* in_sizes, int n_in,
                              void* d_out, int out_size)
{
    const float* x         = (const float*)d_in[0];
    const float* cond      = (const float*)d_in[1];
    const float* pos       = (const float*)d_in[2];
    const float* rms_scale = (const float*)d_in[3];
    const float* W_cond    = (const float*)d_in[4];
    const float* W_qkv     = (const float*)d_in[5];
    const float* W_out     = (const float*)d_in[6];
    float* out = (float*)d_out;

    float *xn, *cp, *xm, *qkv, *q, *kT, *v, *att;
    cudaGetSymbolAddress((void**)&xn,  g_xn);
    cudaGetSymbolAddress((void**)&cp,  g_cp);
    cudaGetSymbolAddress((void**)&xm,  g_xm);
    cudaGetSymbolAddress((void**)&qkv, g_qkv);
    cudaGetSymbolAddress((void**)&q,   g_q);
    cudaGetSymbolAddress((void**)&kT,  g_kT);
    cudaGetSymbolAddress((void**)&v,   g_v);
    cudaGetSymbolAddress((void**)&att, g_att);

    static bool attr_set = false;
    if (!attr_set) {
        cudaFuncSetAttribute(flash_kernel,
                             cudaFuncAttributeMaxDynamicSharedMemorySize,
                             F_TOT * sizeof(float));
        attr_set = true;
    }

    // 1. RMSNorm
    rmsnorm_kernel<<<BL, 256>>>(x, rms_scale, xn);

    // 2. cond projection: cp = cond @ W_cond   (4096 x 3072 x 1024)
    mma_gemm<128, 128, false><<<dim3(24, 32, 1), 256>>>(
        cond, W_cond, cp, DD, DD, 3 * DD, 3 * DD,
        0, 0, 1, 0, 0, nullptr, nullptr);

    // 3. modulate
    modulate_kernel<<<(BL * DD) / 256, 256>>>(xn, cp, xm);

    // 4. qkv projection
    mma_gemm<128, 128, false><<<dim3(24, 32, 1), 256>>>(
        xm, W_qkv, qkv, DD, DD, 3 * DD, 3 * DD,
        0, 0, 1, 0, 0, nullptr, nullptr);

    // 5. RoPE + head scatter (q pre-scaled by 1/8, k transposed)
    rope_kernel<<<BL, 256>>>(qkv, pos, q, kT, v);

    // 6-8. flash attention -> att [B,L,D]
    flash_kernel<<<dim3(LL / 128, BB * HH), 256, F_TOT * sizeof(float)>>>(
        q, kT, v, att);

    // 9. out projection + residual + gate (fused epilogue)
    mma_gemm<128, 128, true><<<dim3(8, 32, 1), 256>>>(
        att, W_out, out, DD, DD, DD, DD,
        0, 0, 1, 0, 0, x, cp);
}

// round 8
// speedup vs baseline: 2.9842x; 1.0367x over previous
#include <cuda_runtime.h>
#include <cuda_bf16.h>
#include <cstdint>

// ---------------------------------------------------------------------------
// Problem constants
// ---------------------------------------------------------------------------
#define BB 2
#define LL 2048
#define DD 1024
#define HH 16
#define HD 64
#define BL (BB*LL)           // 4096
#define EPS 1e-6f

// ---------------------------------------------------------------------------
// Scratch
// ---------------------------------------------------------------------------
__device__ float g_xn [BL*DD];
__device__ float g_cp [BL*3*DD];
__device__ float g_xm [BL*DD];
__device__ float g_qkv[BL*3*DD];
__device__ float g_q  [BL*DD];             // [B,H,L,HD], pre-scaled by 1/8
__device__ float g_kT [BL*DD];             // [B,H,HD,L]
__device__ float g_v  [BL*DD];             // [B,H,L,HD]
__device__ float g_att[BL*DD];             // attn out [B,L,D]

// ---------------------------------------------------------------------------
// helpers
// ---------------------------------------------------------------------------
__device__ __forceinline__ float to_tf32(float x) {
    uint32_t r;
    asm("cvt.rna.tf32.f32 %0, %1;" : "=r"(r) : "f"(x));
    return __uint_as_float(r);
}

__device__ __forceinline__ void mma_tf32(float acc[4],
                                         uint32_t a0, uint32_t a1, uint32_t a2, uint32_t a3,
                                         uint32_t b0, uint32_t b1) {
    asm volatile(
        "mma.sync.aligned.m16n8k8.row.col.f32.tf32.tf32.f32 "
        "{%0,%1,%2,%3}, {%4,%5,%6,%7}, {%8,%9}, {%0,%1,%2,%3};\n"
        : "+f"(acc[0]), "+f"(acc[1]), "+f"(acc[2]), "+f"(acc[3])
        : "r"(a0), "r"(a1), "r"(a2), "r"(a3), "r"(b0), "r"(b1));
}

__device__ __forceinline__ uint32_t smem_u32(const void* p) {
    return (uint32_t)__cvta_generic_to_shared(p);
}

#define CP_ASYNC16(dst_u32, src_ptr) \
    asm volatile("cp.async.cg.shared.global [%0], [%1], 16;\n" \
                 :: "r"(dst_u32), "l"(src_ptr))
#define CP_COMMIT() asm volatile("cp.async.commit_group;\n")
#define CP_WAIT2()  asm volatile("cp.async.wait_group 2;\n")

// GEMM smem sizing (BM=128, BN=128, BK=16, 3 stages) — dynamic smem
#define G_BK    16
#define G_NST   3
#define G_ASTR  (G_BK + 4)          // 20
#define G_BSTR  (128 + 8)           // 136
#define G_ASZ   (128 * G_ASTR)      // 2560 floats
#define G_BSZ   (G_BK * G_BSTR)     // 2176 floats
#define MMA_SMEM_BYTES ((G_NST * (G_ASZ + G_BSZ)) * (int)sizeof(float))  // 56832

// ---------------------------------------------------------------------------
// Batched tf32 tensor-core GEMM (NN) with 3-stage cp.async pipeline.
//   C[z] = A[z] @ B[z].  Operands consumed as tf32 via HW truncation.
//   Dynamic smem (57 KB > 48 KB static cap).
//   EPI: out-projection epilogue  C += residual + gate.
// ---------------------------------------------------------------------------
template<int BM, int BN, bool EPI>
__global__ void __launch_bounds__(256)
mma_gemm(const float* __restrict__ A, const float* __restrict__ Bg,
         float* __restrict__ C,
         int K, int lda, int ldb, int ldc,
         long sA, long sB, int zmod, long sC_hi, long sC_lo,
         const float* __restrict__ Rres, const float* __restrict__ Gg)
{
    constexpr int BK = G_BK;
    constexpr int NST = G_NST;
    constexpr int WM = BM / 2;
    constexpr int WN = BN / 4;
    constexpr int MA = WM / 16;
    constexpr int NA = WN / 8;
    constexpr int ASTR = G_ASTR;
    constexpr int BSTR = BN + 8;
    constexpr int ASZ = BM * ASTR;
    constexpr int BSZ = BK * BSTR;

    extern __shared__ float gsm[];
    float* As = gsm;                    // NST * ASZ
    float* Bs = gsm + NST * ASZ;        // NST * BSZ

    const int z = blockIdx.z;
    A += (long)z * sA;
    Bg += (long)z * sB;
    C += (long)(z / zmod) * sC_hi + (long)(z % zmod) * sC_lo;

    const int bm = blockIdx.y * BM;
    const int bn = blockIdx.x * BN;
    const int tid = threadIdx.x;
    const int lane = tid & 31;
    const int warp = tid >> 5;
    const int wm = warp >> 2;
    const int wn = warp & 3;
    const int g  = lane >> 2;
    const int tg = lane & 3;

    constexpr int A_IT = BM * BK / 1024;          // 2
    constexpr int A_RSTEP = 1024 / BK;            // 64
    const int arow = tid / (BK / 4);
    const int acol = (tid % (BK / 4)) * 4;
    constexpr int B_IT = BK * BN / 1024;          // 2 (BN=128)
    constexpr int B_RSTEP = 1024 / BN;            // 8
    const int brow = tid / (BN / 4);
    const int bcol = (tid % (BN / 4)) * 4;

    float acc[MA][NA][4];
#pragma unroll
    for (int i = 0; i < MA; i++)
#pragma unroll
        for (int j = 0; j < NA; j++)
#pragma unroll
            for (int c = 0; c < 4; c++) acc[i][j][c] = 0.f;

    const int nk = K / BK;

    // prologue: fill the pipeline
#pragma unroll
    for (int s = 0; s < NST; s++) {
        if (s < nk) {
            float* dA = As + s * ASZ;
            float* dB = Bs + s * BSZ;
#pragma unroll
            for (int i = 0; i < A_IT; i++)
                CP_ASYNC16(smem_u32(&dA[(arow + i * A_RSTEP) * ASTR + acol]),
                           &A[(long)(bm + arow + i * A_RSTEP) * lda + s * BK + acol]);
#pragma unroll
            for (int i = 0; i < B_IT; i++)
                CP_ASYNC16(smem_u32(&dB[(brow + i * B_RSTEP) * BSTR + bcol]),
                           &Bg[(long)(s * BK + brow + i * B_RSTEP) * ldb + bn + bcol]);
        }
        CP_COMMIT();
    }

    for (int it = 0; it < nk; it++) {
        CP_WAIT2();
        __syncthreads();

        const int buf = it % NST;
        const float* cA = As + buf * ASZ;
        const float* cB = Bs + buf * BSZ;

#pragma unroll
        for (int ks = 0; ks < 2; ks++) {
            uint32_t af[MA][4], bf[NA][2];
#pragma unroll
            for (int i = 0; i < MA; i++) {
                const int r0 = (wm * WM + i * 16 + g) * ASTR + ks * 8 + tg;
                const int r1 = r0 + 8 * ASTR;
                af[i][0] = __float_as_uint(cA[r0]);
                af[i][1] = __float_as_uint(cA[r1]);
                af[i][2] = __float_as_uint(cA[r0 + 4]);
                af[i][3] = __float_as_uint(cA[r1 + 4]);
            }
#pragma unroll
            for (int j = 0; j < NA; j++) {
                const int c0 = (ks * 8 + tg) * BSTR + wn * WN + j * 8 + g;
                bf[j][0] = __float_as_uint(cB[c0]);
                bf[j][1] = __float_as_uint(cB[c0 + 4 * BSTR]);
            }
#pragma unroll
            for (int i = 0; i < MA; i++)
#pragma unroll
                for (int j = 0; j < NA; j++)
                    mma_tf32(acc[i][j], af[i][0], af[i][1], af[i][2], af[i][3],
                             bf[j][0], bf[j][1]);
        }
        __syncthreads();   // everyone done with buf before refilling it

        const int t = it + NST;
        if (t < nk) {
            float* dA = As + buf * ASZ;
            float* dB = Bs + buf * BSZ;
#pragma unroll
            for (int i = 0; i < A_IT; i++)
                CP_ASYNC16(smem_u32(&dA[(arow + i * A_RSTEP) * ASTR + acol]),
                           &A[(long)(bm + arow + i * A_RSTEP) * lda + t * BK + acol]);
#pragma unroll
            for (int i = 0; i < B_IT; i++)
                CP_ASYNC16(smem_u32(&dB[(brow + i * B_RSTEP) * BSTR + bcol]),
                           &Bg[(long)(t * BK + brow + i * B_RSTEP) * ldb + bn + bcol]);
        }
        CP_COMMIT();
    }

    // epilogue
#pragma unroll
    for (int i = 0; i < MA; i++) {
        const int r0 = bm + wm * WM + i * 16 + g;
#pragma unroll
        for (int j = 0; j < NA; j++) {
            const int c = bn + wn * WN + j * 8 + tg * 2;
            float2 v0 = make_float2(acc[i][j][0], acc[i][j][1]);
            float2 v1 = make_float2(acc[i][j][2], acc[i][j][3]);
            if (EPI) {
                v0.x += Rres[(long)r0 * DD + c]     + Gg[(long)r0 * 3 * DD + 3 * c + 2];
                v0.y += Rres[(long)r0 * DD + c + 1] + Gg[(long)r0 * 3 * DD + 3 * (c + 1) + 2];
                v1.x += Rres[(long)(r0 + 8) * DD + c]     + Gg[(long)(r0 + 8) * 3 * DD + 3 * c + 2];
                v1.y += Rres[(long)(r0 + 8) * DD + c + 1] + Gg[(long)(r0 + 8) * 3 * DD + 3 * (c + 1) + 2];
            }
            *reinterpret_cast<float2*>(&C[(long)r0 * ldc + c]) = v0;
            *reinterpret_cast<float2*>(&C[(long)(r0 + 8) * ldc + c]) = v1;
        }
    }
}

// ---------------------------------------------------------------------------
// Flash attention (verified R5; unchanged)
// ---------------------------------------------------------------------------
#define FQ_STR 68
#define FB_STR 72
#define F_SQ   0
#define F_SK   (128*FQ_STR)
#define F_SV   (F_SK + 64*FB_STR)
#define F_SP   (F_SV + 64*FB_STR)
#define F_TOT  (F_SP + 128*FQ_STR)

__global__ void __launch_bounds__(256)
flash_kernel(const float* __restrict__ q, const float* __restrict__ kT,
             const float* __restrict__ v, float* __restrict__ att)
{
    extern __shared__ float sm[];
    float* sQ = sm + F_SQ;
    float* sK = sm + F_SK;
    float* sV = sm + F_SV;
    float* sP = sm + F_SP;

    const int bh = blockIdx.y;
    const int b  = bh >> 4;
    const int h  = bh & (HH - 1);
    const int m0 = blockIdx.x * 128;
    const int tid = threadIdx.x;
    const int lane = tid & 31;
    const int warp = tid >> 5;
    const int g  = lane >> 2;
    const int tg = lane & 3;

    const float* qbase = q + ((long)bh * LL + m0) * HD;
    for (int i = tid; i < 128 * 16; i += 256) {
        const int r = i >> 4, c4 = (i & 15) * 4;
        float4 t = *reinterpret_cast<const float4*>(&qbase[(long)r * HD + c4]);
        float* d = &sQ[r * FQ_STR + c4];
        d[0] = to_tf32(t.x); d[1] = to_tf32(t.y);
        d[2] = to_tf32(t.z); d[3] = to_tf32(t.w);
    }

    float accO[8][4];
#pragma unroll
    for (int j = 0; j < 8; j++)
#pragma unroll
        for (int c = 0; c < 4; c++) accO[j][c] = 0.f;
    float mrow0 = -1e30f, mrow1 = -1e30f, lrow0 = 0.f, lrow1 = 0.f;

    const float* kbase = kT + (long)bh * HD * LL;
    const float* vbase = v + (long)bh * LL * HD;
    const int prow = (warp * 16 + g) * FQ_STR;

    for (int j0 = 0; j0 < LL; j0 += 64) {
        __syncthreads();
        for (int i = tid; i < 64 * 16; i += 256) {
            const int r = i >> 4, c4 = (i & 15) * 4;
            float4 t = *reinterpret_cast<const float4*>(&kbase[(long)r * LL + j0 + c4]);
            float* d = &sK[r * FB_STR + c4];
            d[0] = to_tf32(t.x); d[1] = to_tf32(t.y);
            d[2] = to_tf32(t.z); d[3] = to_tf32(t.w);
        }
        for (int i = tid; i < 64 * 16; i += 256) {
            const int r = i >> 4, c4 = (i & 15) * 4;
            float4 t = *reinterpret_cast<const float4*>(&vbase[(long)(j0 + r) * HD + c4]);
            float* d = &sV[r * FB_STR + c4];
            d[0] = to_tf32(t.x); d[1] = to_tf32(t.y);
            d[2] = to_tf32(t.z); d[3] = to_tf32(t.w);
        }
        __syncthreads();

        float s[8][4];
#pragma unroll
        for (int j = 0; j < 8; j++)
#pragma unroll
            for (int c = 0; c < 4; c++) s[j][c] = 0.f;
#pragma unroll
        for (int ks = 0; ks < 8; ks++) {
            const int r0 = prow + ks * 8 + tg;
            const uint32_t a0 = __float_as_uint(sQ[r0]);
            const uint32_t a1 = __float_as_uint(sQ[r0 + 8 * FQ_STR]);
            const uint32_t a2 = __float_as_uint(sQ[r0 + 4]);
            const uint32_t a3 = __float_as_uint(sQ[r0 + 8 * FQ_STR + 4]);
#pragma unroll
            for (int j = 0; j < 8; j++) {
                const int c0 = (ks * 8 + tg) * FB_STR + j * 8 + g;
                mma_tf32(s[j], a0, a1, a2, a3,
                         __float_as_uint(sK[c0]),
                         __float_as_uint(sK[c0 + 4 * FB_STR]));
            }
        }

        float mx0 = -1e30f, mx1 = -1e30f;
#pragma unroll
        for (int j = 0; j < 8; j++) {
            mx0 = fmaxf(mx0, fmaxf(s[j][0], s[j][1]));
            mx1 = fmaxf(mx1, fmaxf(s[j][2], s[j][3]));
        }
        mx0 = fmaxf(mx0, __shfl_xor_sync(~0u, mx0, 1));
        mx0 = fmaxf(mx0, __shfl_xor_sync(~0u, mx0, 2));
        mx1 = fmaxf(mx1, __shfl_xor_sync(~0u, mx1, 1));
        mx1 = fmaxf(mx1, __shfl_xor_sync(~0u, mx1, 2));

        const float mn0 = fmaxf(mrow0, mx0);
        const float mn1 = fmaxf(mrow1, mx1);
        const float al0 = __expf(mrow0 - mn0);
        const float al1 = __expf(mrow1 - mn1);
        mrow0 = mn0; mrow1 = mn1;

        float ps0 = 0.f, ps1 = 0.f;
#pragma unroll
        for (int j = 0; j < 8; j++) {
            s[j][0] = __expf(s[j][0] - mn0);
            s[j][1] = __expf(s[j][1] - mn0);
            s[j][2] = __expf(s[j][2] - mn1);
            s[j][3] = __expf(s[j][3] - mn1);
            ps0 += s[j][0] + s[j][1];
            ps1 += s[j][2] + s[j][3];
        }
        ps0 += __shfl_xor_sync(~0u, ps0, 1);
        ps0 += __shfl_xor_sync(~0u, ps0, 2);
        ps1 += __shfl_xor_sync(~0u, ps1, 1);
        ps1 += __shfl_xor_sync(~0u, ps1, 2);
        lrow0 = lrow0 * al0 + ps0;
        lrow1 = lrow1 * al1 + ps1;

#pragma unroll
        for (int j = 0; j < 8; j++) {
            accO[j][0] *= al0; accO[j][1] *= al0;
            accO[j][2] *= al1; accO[j][3] *= al1;
        }

#pragma unroll
        for (int j = 0; j < 8; j++) {
            const int c = j * 8 + tg * 2;
            sP[prow + c]     = to_tf32(s[j][0]);
            sP[prow + c + 1] = to_tf32(s[j][1]);
            sP[prow + 8 * FQ_STR + c]     = to_tf32(s[j][2]);
            sP[prow + 8 * FQ_STR + c + 1] = to_tf32(s[j][3]);
        }
        __syncwarp();

#pragma unroll
        for (int ks = 0; ks < 8; ks++) {
            const int r0 = prow + ks * 8 + tg;
            const uint32_t a0 = __float_as_uint(sP[r0]);
            const uint32_t a1 = __float_as_uint(sP[r0 + 8 * FQ_STR]);
            const uint32_t a2 = __float_as_uint(sP[r0 + 4]);
            const uint32_t a3 = __float_as_uint(sP[r0 + 8 * FQ_STR + 4]);
#pragma unroll
            for (int j = 0; j < 8; j++) {
                const int c0 = (ks * 8 + tg) * FB_STR + j * 8 + g;
                mma_tf32(accO[j], a0, a1, a2, a3,
                         __float_as_uint(sV[c0]),
                         __float_as_uint(sV[c0 + 4 * FB_STR]));
            }
        }
    }

    const float inv0 = 1.f / lrow0;
    const float inv1 = 1.f / lrow1;
    float* obase = att + ((long)(b * LL + m0 + warp * 16 + g)) * DD + h * HD;
#pragma unroll
    for (int j = 0; j < 8; j++) {
        const int c = j * 8 + tg * 2;
        *reinterpret_cast<float2*>(&obase[c]) =
            make_float2(accO[j][0] * inv0, accO[j][1] * inv0);
        *reinterpret_cast<float2*>(&obase[(long)8 * DD + c]) =
            make_float2(accO[j][2] * inv1, accO[j][3] * inv1);
    }
}

// ---------------------------------------------------------------------------
// RMSNorm
// ---------------------------------------------------------------------------
__global__ void rmsnorm_kernel(const float* __restrict__ x,
                               const float* __restrict__ scale,
                               float* __restrict__ out)
{
    const int row = blockIdx.x;
    const float4 a = *((const float4*)(x + (long)row * DD) + threadIdx.x);
    float ss = a.x * a.x + a.y * a.y + a.z * a.z + a.w * a.w;

    __shared__ float red[8];
    for (int o = 16; o > 0; o >>= 1) ss += __shfl_xor_sync(~0u, ss, o);
    if ((threadIdx.x & 31) == 0) red[threadIdx.x >> 5] = ss;
    __syncthreads();
    __shared__ float rinv;
    if (threadIdx.x == 0) {
        float t = 0.f;
#pragma unroll
        for (int i = 0; i < 8; i++) t += red[i];
        rinv = rsqrtf(t * (1.0f / DD) + EPS);
    }
    __syncthreads();

    const float4 sc = *((const float4*)scale + threadIdx.x);
    float4 o4;
    o4.x = a.x * rinv * sc.x; o4.y = a.y * rinv * sc.y;
    o4.z = a.z * rinv * sc.z; o4.w = a.w * rinv * sc.w;
    *((float4*)(out + (long)row * DD) + threadIdx.x) = o4;
}

// ---------------------------------------------------------------------------
// AdaLN modulation
// ---------------------------------------------------------------------------
__global__ void modulate_kernel(const float* __restrict__ xn,
                                const float* __restrict__ cp,
                                float* __restrict__ xm)
{
    const int idx = blockIdx.x * blockDim.x + threadIdx.x;
    const int row = idx >> 10;
    const int d = idx & 1023;
    const long base = (long)row * (3 * DD) + 3 * d;
    xm[idx] = xn[idx] * (1.f + cp[base]) + cp[base + 1];
}

// ---------------------------------------------------------------------------
// RoPE + head scatter
// ---------------------------------------------------------------------------
__global__ void rope_kernel(const float* __restrict__ qkv,
                            const float* __restrict__ pos,
                            float* __restrict__ q,
                            float* __restrict__ kT,
                            float* __restrict__ v)
{
    const int bl = blockIdx.x;
    const int b = bl >> 11;
    const int l = bl & (LL - 1);
    __shared__ float srow[3 * DD];
    __shared__ float spos[2 * HD];

    const float4* src = (const float4*)(qkv + (long)bl * (3 * DD));
    for (int i = threadIdx.x; i < (3 * DD) / 4; i += blockDim.x)
        ((float4*)srow)[i] = src[i];
    if (threadIdx.x < (2 * HD) / 4)
        ((float4*)spos)[threadIdx.x] =
            ((const float4*)(pos + (long)bl * (2 * HD)))[threadIdx.x];
    __syncthreads();

    for (int idx = threadIdx.x; idx < DD; idx += blockDim.x) {
        const int h = idx >> 6;
        const int d = idx & (HD - 1);
        const int c = (d * HH + h) * 3;
        const int dp = (d < HD / 2) ? d + HD / 2 : d - HD / 2;
        const int c2 = (dp * HH + h) * 3;
        const float sgn = (d < HD / 2) ? -1.f : 1.f;
        const float s = spos[2 * d];
        const float ct = spos[2 * d + 1];

        const float qo = srow[c] * ct + sgn * srow[c2] * s;
        const float ko = srow[c + 1] * ct + sgn * srow[c2 + 1] * s;

        const long o = ((long)(b * HH + h) * LL + l) * HD + d;
        q[o] = qo * 0.125f;
        kT[((long)(b * HH + h) * HD + d) * LL + l] = ko;
        v[o] = srow[c + 2];
    }
}

// ---------------------------------------------------------------------------
// Launch
// ---------------------------------------------------------------------------
extern "C" void kernel_launch(void* const* d_in, const int* in_sizes, int n_in,
                              void* d_out, int out_size)
{
    const float* x         = (const float*)d_in[0];
    const float* cond      = (const float*)d_in[1];
    const float* pos       = (const float*)d_in[2];
    const float* rms_scale = (const float*)d_in[3];
    const float* W_cond    = (const float*)d_in[4];
    const float* W_qkv     = (const float*)d_in[5];
    const float* W_out     = (const float*)d_in[6];
    float* out = (float*)d_out;

    float *xn, *cp, *xm, *qkv, *q, *kT, *v, *att;
    cudaGetSymbolAddress((void**)&xn,  g_xn);
    cudaGetSymbolAddress((void**)&cp,  g_cp);
    cudaGetSymbolAddress((void**)&xm,  g_xm);
    cudaGetSymbolAddress((void**)&qkv, g_qkv);
    cudaGetSymbolAddress((void**)&q,   g_q);
    cudaGetSymbolAddress((void**)&kT,  g_kT);
    cudaGetSymbolAddress((void**)&v,   g_v);
    cudaGetSymbolAddress((void**)&att, g_att);

    static bool attr_set = false;
    if (!attr_set) {
        cudaFuncSetAttribute(flash_kernel,
                             cudaFuncAttributeMaxDynamicSharedMemorySize,
                             F_TOT * sizeof(float));
        cudaFuncSetAttribute(mma_gemm<128, 128, false>,
                             cudaFuncAttributeMaxDynamicSharedMemorySize,
                             MMA_SMEM_BYTES);
        cudaFuncSetAttribute(mma_gemm<128, 128, true>,
                             cudaFuncAttributeMaxDynamicSharedMemorySize,
                             MMA_SMEM_BYTES);
        attr_set = true;
    }

    // 1. RMSNorm
    rmsnorm_kernel<<<BL, 256>>>(x, rms_scale, xn);

    // 2. cond projection
    mma_gemm<128, 128, false><<<dim3(24, 32, 1), 256, MMA_SMEM_BYTES>>>(
        cond, W_cond, cp, DD, DD, 3 * DD, 3 * DD,
        0, 0, 1, 0, 0, nullptr, nullptr);

    // 3. modulate
    modulate_kernel<<<(BL * DD) / 256, 256>>>(xn, cp, xm);

    // 4. qkv projection
    mma_gemm<128, 128, false><<<dim3(24, 32, 1), 256, MMA_SMEM_BYTES>>>(
        xm, W_qkv, qkv, DD, DD, 3 * DD, 3 * DD,
        0, 0, 1, 0, 0, nullptr, nullptr);

    // 5. RoPE + head scatter
    rope_kernel<<<BL, 256>>>(qkv, pos, q, kT, v);

    // 6-8. flash attention -> att [B,L,D]
    flash_kernel<<<dim3(LL / 128, BB * HH), 256, F_TOT * sizeof(float)>>>(
        q, kT, v, att);

    // 9. out projection + residual + gate
    mma_gemm<128, 128, true><<<dim3(8, 32, 1), 256, MMA_SMEM_BYTES>>>(
        att, W_out, out, DD, DD, DD, DD,
        0, 0, 1, 0, 0, x, cp);
}